// round 17
// baseline (speedup 1.0000x reference)
#include <cuda_runtime.h>
#include <cuda_fp16.h>
#include <cstdint>

// ============================================================================
// Problem constants
// ============================================================================
#define BATCH 8
#define SEQ   1024
#define DIM   1024
#define HDIM  64

// ============================================================================
// Scratch (half + fp32 scores), element offsets
// ============================================================================
#define H1M (1u << 20)
#define XH  (0u  * H1M)   // hidden as fp16          (8M)
#define RH  (8u  * H1M)   // right as fp16           (8M)
#define QH  (16u * H1M)   // Q fp16 (scaled 0.125)   (8M)
#define KH  (24u * H1M)   // K fp16                  (8M)
#define VH  (32u * H1M)   // V fp16 [s][d]           (8M)
#define VTH (40u * H1M)   // V^T fp16 [d][s]         (8M)
#define PH  (48u * H1M)   // probs fp16              (8M)
#define WQ  (56u * H1M)   // Wq^T fp16 [n][k]; WK=+1M, WV=+2M

__device__ __align__(256) __half g_half[59u * H1M];
__device__ __align__(256) float  g_scores[8u * H1M];   // fp32 scores (32MB)

// ============================================================================
// GEMM tiling
// ============================================================================
#define BM     128
#define BN     128
#define BKH    64                 // halfs of K per stage (128 B/row)
#define SA     72                 // padded smem row stride (halfs, 144 B)
#define STAGES 3
#define NKI    (1024 / BKH)       // 16
#define SMEM_BYTES (STAGES * (BM + BN) * SA * 2)   // 110592 -> 2 CTAs/SM

// ============================================================================
// Device helpers
// ============================================================================
__device__ __forceinline__ uint32_t smem_u32(const void* p) {
    uint32_t a;
    asm("{ .reg .u64 t; cvta.to.shared.u64 t, %1; cvt.u32.u64 %0, t; }"
        : "=r"(a) : "l"(p));
    return a;
}

__device__ __forceinline__ void cp_async16(uint32_t saddr, const void* gaddr) {
    asm volatile("cp.async.cg.shared.global [%0], [%1], 16;"
                 :: "r"(saddr), "l"(gaddr) : "memory");
}

#define LDSM4(r0, r1, r2, r3, addr) \
    asm volatile("ldmatrix.sync.aligned.m8n8.x4.shared.b16 {%0,%1,%2,%3}, [%4];" \
                 : "=r"(r0), "=r"(r1), "=r"(r2), "=r"(r3) : "r"(addr))

__device__ __forceinline__ void mma16816(float* c, const uint32_t* a,
                                         const uint32_t* b) {
    asm volatile(
        "mma.sync.aligned.m16n8k16.row.col.f32.f16.f16.f32 "
        "{%0,%1,%2,%3}, {%4,%5,%6,%7}, {%8,%9}, {%0,%1,%2,%3};"
        : "+f"(c[0]), "+f"(c[1]), "+f"(c[2]), "+f"(c[3])
        : "r"(a[0]), "r"(a[1]), "r"(a[2]), "r"(a[3]), "r"(b[0]), "r"(b[1]));
}

// ============================================================================
// fp16 tensor-core GEMM:  D[BM x BN] = A[BM x 1024] . B[BN x 1024]^T
// (A row-major halfs, B K-major halfs; fp32 accumulate)
// MODE 0: merged projections (z: 0=Q,1=K,2=V), half output with bias+alpha
// MODE 1: scores -> g_scores fp32
// MODE 2: context -> permuted fp32 out
//
// Single-barrier cp.async pipeline: prologue fills STAGES-1 stages; each
// iteration waits for its stage, syncs once, issues the refill for stage
// (ks+STAGES-1)%STAGES (the one computed in iteration ks-1 -- safe because
// every warp passed this iteration's barrier only after finishing it),
// commits, then computes.
// ============================================================================
template <int MODE>
__global__ __launch_bounds__(256, 2)
void hgemm(const float* __restrict__ b0, const float* __restrict__ b1,
           const float* __restrict__ b2, float* __restrict__ outp) {
    extern __shared__ __half smh[];
    __half* As = smh;                            // [STAGES][BM][SA]
    __half* Bs = smh + STAGES * BM * SA;         // [STAGES][BN][SA]
    uint32_t sAb = smem_u32(As);
    uint32_t sBb = smem_u32(Bs);

    int tid = threadIdx.x;
    int wid = tid >> 5, lane = tid & 31;
    int wm = wid >> 2, wn = wid & 3;             // 2 x 4 warp grid
    int bx = blockIdx.x, by = blockIdx.y, bz = blockIdx.z;

    // ---- resolve operands from scratch ----
    const __half *Ag, *Bg;
    if (MODE == 0) {
        Ag = g_half + (bz == 0 ? XH : RH) + (size_t)by * BM * 1024;
        Bg = g_half + WQ + (size_t)bz * H1M + (size_t)bx * BN * 1024;
    } else if (MODE == 1) {
        Ag = g_half + QH + (size_t)bz * H1M + (size_t)by * BM * 1024;
        Bg = g_half + KH + (size_t)bz * H1M + (size_t)bx * BN * 1024;
    } else {
        Ag = g_half + PH + (size_t)bz * H1M + (size_t)by * BM * 1024;
        Bg = g_half + VTH + (size_t)bz * H1M + (size_t)bx * BN * 1024;
    }

    // ---- loader assignments: 1024 16B-chunks per matrix per stage ----
    int ldrow[4], ldc[4];
#pragma unroll
    for (int i = 0; i < 4; i++) {
        int idx = i * 256 + tid;
        ldrow[i] = idx >> 3;
        ldc[i] = idx & 7;
    }

    // ---- fragment smem byte offsets (within one stage) ----
    int r8 = lane & 7;
    int a_row = ((lane >> 3) & 1) * 8 + r8;
    int a_k   = (lane >> 4) * 8;
    uint32_t aoff[4];
#pragma unroll
    for (int mi = 0; mi < 4; mi++)
        aoff[mi] = ((wm * 64 + mi * 16 + a_row) * SA + a_k) * 2;
    int b_n = ((lane >> 4) & 1) * 8 + r8;
    int b_k = ((lane >> 3) & 1) * 8;
    uint32_t boff[2];
#pragma unroll
    for (int g = 0; g < 2; g++)
        boff[g] = ((wn * 32 + g * 16 + b_n) * SA + b_k) * 2;

    float acc[4][4][4];
#pragma unroll
    for (int mi = 0; mi < 4; mi++)
#pragma unroll
        for (int ni = 0; ni < 4; ni++)
#pragma unroll
            for (int c = 0; c < 4; c++) acc[mi][ni][c] = 0.0f;

    // ---- prologue: fill STAGES-1 stages ----
#pragma unroll
    for (int s = 0; s < STAGES - 1; s++) {
#pragma unroll
        for (int i = 0; i < 4; i++) {
            uint32_t so = (uint32_t)(ldrow[i] * SA + ldc[i] * 8) * 2;
            uint32_t sb = (uint32_t)(s * BM * SA * 2);
            cp_async16(sAb + sb + so, Ag + (size_t)ldrow[i] * 1024 + s * BKH + ldc[i] * 8);
            cp_async16(sBb + sb + so, Bg + (size_t)ldrow[i] * 1024 + s * BKH + ldc[i] * 8);
        }
        asm volatile("cp.async.commit_group;" ::: "memory");
    }

    // ---- main loop: ONE barrier per iteration ----
    for (int ks = 0; ks < NKI; ks++) {
        int st = ks % STAGES;
        asm volatile("cp.async.wait_group %0;" :: "n"(STAGES - 2) : "memory");
        __syncthreads();

        // refill stage (ks + STAGES - 1) % STAGES (computed in iter ks-1)
        int kn = ks + STAGES - 1;
        if (kn < NKI) {
            int sd = kn % STAGES;
#pragma unroll
            for (int i = 0; i < 4; i++) {
                uint32_t so = (uint32_t)(ldrow[i] * SA + ldc[i] * 8) * 2;
                uint32_t sb = (uint32_t)(sd * BM * SA * 2);
                cp_async16(sAb + sb + so,
                           Ag + (size_t)ldrow[i] * 1024 + kn * BKH + ldc[i] * 8);
                cp_async16(sBb + sb + so,
                           Bg + (size_t)ldrow[i] * 1024 + kn * BKH + ldc[i] * 8);
            }
        }
        asm volatile("cp.async.commit_group;" ::: "memory");

        uint32_t Ast = sAb + (uint32_t)(st * BM * SA * 2);
        uint32_t Bst = sBb + (uint32_t)(st * BN * SA * 2);

#pragma unroll
        for (int k16 = 0; k16 < BKH / 16; k16++) {
            uint32_t kk = k16 * 32;   // 16 halfs = 32 bytes
            uint32_t afr[4][4];
#pragma unroll
            for (int mi = 0; mi < 4; mi++)
                LDSM4(afr[mi][0], afr[mi][1], afr[mi][2], afr[mi][3],
                      Ast + aoff[mi] + kk);
            uint32_t bfr[4][2];
            LDSM4(bfr[0][0], bfr[0][1], bfr[1][0], bfr[1][1], Bst + boff[0] + kk);
            LDSM4(bfr[2][0], bfr[2][1], bfr[3][0], bfr[3][1], Bst + boff[1] + kk);
#pragma unroll
            for (int mi = 0; mi < 4; mi++)
#pragma unroll
                for (int ni = 0; ni < 4; ni++)
                    mma16816(acc[mi][ni], afr[mi], bfr[ni]);
        }
    }

    // ---- epilogue ----
    int crow = lane >> 2;
    int ccol = (lane & 3) * 2;

    if (MODE == 0) {
        const float* bias = (bz == 0) ? b0 : (bz == 1 ? b1 : b2);
        float alpha = (bz == 0) ? 0.125f : 1.0f;
        __half* Ch = g_half + QH + (size_t)bz * 8 * H1M;
#pragma unroll
        for (int mi = 0; mi < 4; mi++) {
            int gm = by * BM + wm * 64 + mi * 16 + crow;
            __half* r0 = Ch + (size_t)gm * 1024;
            __half* r1 = r0 + (size_t)8 * 1024;
#pragma unroll
            for (int ni = 0; ni < 4; ni++) {
                int gn = bx * BN + wn * 32 + ni * 8 + ccol;
                const float* a4 = acc[mi][ni];
                float bb0 = bias[gn], bb1 = bias[gn + 1];
                *(half2*)(r0 + gn) =
                    __floats2half2_rn(alpha * (a4[0] + bb0), alpha * (a4[1] + bb1));
                *(half2*)(r1 + gn) =
                    __floats2half2_rn(alpha * (a4[2] + bb0), alpha * (a4[3] + bb1));
            }
        }
    } else if (MODE == 1) {
        float* Cf = g_scores + (size_t)bz * H1M;
#pragma unroll
        for (int mi = 0; mi < 4; mi++) {
            int gm = by * BM + wm * 64 + mi * 16 + crow;
            float* r0 = Cf + (size_t)gm * 1024;
            float* r1 = r0 + (size_t)8 * 1024;
#pragma unroll
            for (int ni = 0; ni < 4; ni++) {
                int gn = bx * BN + wn * 32 + ni * 8 + ccol;
                const float* a4 = acc[mi][ni];
                *(float2*)(r0 + gn) = make_float2(a4[0], a4[1]);
                *(float2*)(r1 + gn) = make_float2(a4[2], a4[3]);
            }
        }
    } else {
        float* obase = outp + (size_t)bz * SEQ * DIM;
#pragma unroll
        for (int mi = 0; mi < 4; mi++) {
            int q = by * BM + wm * 64 + mi * 16 + crow;
#pragma unroll
            for (int ni = 0; ni < 4; ni++) {
                int gn = bx * BN + wn * 32 + ni * 8 + ccol;
                int h = gn >> 6, dh = gn & 63;
                float* dst = obase + ((size_t)h * SEQ + q) * HDIM + dh;
                const float* a4 = acc[mi][ni];
                *(float2*)dst = make_float2(a4[0], a4[1]);
                *(float2*)(dst + (size_t)8 * HDIM) = make_float2(a4[2], a4[3]);
            }
        }
    }
}

// ============================================================================
// fp32 -> fp16 copy (8 elems / thread)
// ============================================================================
__global__ __launch_bounds__(256)
void f2h(const float4* __restrict__ src, __half* __restrict__ dst) {
    size_t i = (size_t)blockIdx.x * 256 + threadIdx.x;
    float4 v0 = src[2 * i];
    float4 v1 = src[2 * i + 1];
    half2 h[4];
    h[0] = __floats2half2_rn(v0.x, v0.y);
    h[1] = __floats2half2_rn(v0.z, v0.w);
    h[2] = __floats2half2_rn(v1.x, v1.y);
    h[3] = __floats2half2_rn(v1.z, v1.w);
    *reinterpret_cast<uint4*>(dst + 8 * i) = *reinterpret_cast<uint4*>(h);
}

// ============================================================================
// 1024x1024 fp32 -> fp16 transpose (z selects one of 3 weight matrices)
// ============================================================================
__global__ __launch_bounds__(256)
void transpose_f2h(const float* __restrict__ w0, const float* __restrict__ w1,
                   const float* __restrict__ w2) {
    __shared__ float t[32][33];
    int bz = blockIdx.z;
    const float* s = (bz == 0) ? w0 : (bz == 1 ? w1 : w2);
    __half* d = g_half + WQ + (size_t)bz * H1M;
    int x = blockIdx.x * 32 + threadIdx.x;
    int y0 = blockIdx.y * 32;
    for (int i = threadIdx.y; i < 32; i += 8)
        t[i][threadIdx.x] = s[(size_t)(y0 + i) * 1024 + x];
    __syncthreads();
    int ox = blockIdx.y * 32 + threadIdx.x;
    int oy0 = blockIdx.x * 32;
    for (int i = threadIdx.y; i < 32; i += 8)
        d[(size_t)(oy0 + i) * 1024 + ox] = __float2half_rn(t[threadIdx.x][i]);
}

// ============================================================================
// per-batch 1024x1024 fp16 transpose: VH [s][d] -> VTH [d][s]
// ============================================================================
__global__ __launch_bounds__(256)
void transpose_h2h() {
    __shared__ __half t[32][34];
    int bz = blockIdx.z;
    const __half* s = g_half + VH + (size_t)bz * H1M;
    __half* d = g_half + VTH + (size_t)bz * H1M;
    int x = blockIdx.x * 32 + threadIdx.x;
    int y0 = blockIdx.y * 32;
    for (int i = threadIdx.y; i < 32; i += 8)
        t[i][threadIdx.x] = s[(size_t)(y0 + i) * 1024 + x];
    __syncthreads();
    int ox = blockIdx.y * 32 + threadIdx.x;
    int oy0 = blockIdx.x * 32;
    for (int i = threadIdx.y; i < 32; i += 8)
        d[(size_t)(oy0 + i) * 1024 + ox] = t[threadIdx.x][i];
}

// ============================================================================
// Masked softmax over fp32 scores rows; writes fp16 probs.
// ============================================================================
__global__ __launch_bounds__(256)
void softmax_kernel(const float* __restrict__ mask) {
    __shared__ float red[8];
    int row = blockIdx.x;
    int b = row >> 10;
    int q = row & (SEQ - 1);
    const float* p = g_scores + (size_t)row * SEQ;
    __half* ph = g_half + PH + (size_t)row * SEQ;
    const float* mrow = mask + ((size_t)b * SEQ + q) * SEQ;

    int t = threadIdx.x;
    float4 s = ((const float4*)p)[t];
    float4 mm = ((const float4*)mrow)[t];
    s.x += (1.0f - mm.x) * -1e9f;
    s.y += (1.0f - mm.y) * -1e9f;
    s.z += (1.0f - mm.z) * -1e9f;
    s.w += (1.0f - mm.w) * -1e9f;

    float v = fmaxf(fmaxf(s.x, s.y), fmaxf(s.z, s.w));
#pragma unroll
    for (int o = 16; o; o >>= 1) v = fmaxf(v, __shfl_xor_sync(0xffffffffu, v, o));
    if ((t & 31) == 0) red[t >> 5] = v;
    __syncthreads();
    if (t < 32) {
        float x = (t < 8) ? red[t] : -3.4e38f;
#pragma unroll
        for (int o = 4; o; o >>= 1) x = fmaxf(x, __shfl_xor_sync(0xffffffffu, x, o));
        if (t == 0) red[0] = x;
    }
    __syncthreads();
    float rmax = red[0];

    float e0 = expf(s.x - rmax);
    float e1 = expf(s.y - rmax);
    float e2 = expf(s.z - rmax);
    float e3 = expf(s.w - rmax);

    __syncthreads();
    float sum = e0 + e1 + e2 + e3;
#pragma unroll
    for (int o = 16; o; o >>= 1) sum += __shfl_xor_sync(0xffffffffu, sum, o);
    if ((t & 31) == 0) red[t >> 5] = sum;
    __syncthreads();
    if (t < 32) {
        float x = (t < 8) ? red[t] : 0.0f;
#pragma unroll
        for (int o = 4; o; o >>= 1) x += __shfl_xor_sync(0xffffffffu, x, o);
        if (t == 0) red[0] = x;
    }
    __syncthreads();
    float inv = 1.0f / red[0];

    half2 h[2];
    h[0] = __floats2half2_rn(e0 * inv, e1 * inv);
    h[1] = __floats2half2_rn(e2 * inv, e3 * inv);
    *reinterpret_cast<uint2*>(ph + 4 * t) = *reinterpret_cast<uint2*>(h);
}

// ============================================================================
// Launch
// ============================================================================
extern "C" void kernel_launch(void* const* d_in, const int* in_sizes, int n_in,
                              void* d_out, int out_size) {
    const float* hidden = (const float*)d_in[0];
    const float* right  = (const float*)d_in[1];
    const float* mask   = (const float*)d_in[2];
    const float* Wq     = (const float*)d_in[3];
    const float* bq     = (const float*)d_in[4];
    const float* Wk     = (const float*)d_in[5];
    const float* bk     = (const float*)d_in[6];
    const float* Wv     = (const float*)d_in[7];
    const float* bv     = (const float*)d_in[8];
    float* out = (float*)d_out;

    __half* Hs = nullptr;
    cudaGetSymbolAddress((void**)&Hs, g_half);

    cudaFuncSetAttribute(hgemm<0>, cudaFuncAttributeMaxDynamicSharedMemorySize,
                         SMEM_BYTES);
    cudaFuncSetAttribute(hgemm<1>, cudaFuncAttributeMaxDynamicSharedMemorySize,
                         SMEM_BYTES);
    cudaFuncSetAttribute(hgemm<2>, cudaFuncAttributeMaxDynamicSharedMemorySize,
                         SMEM_BYTES);

    // 1) inputs -> fp16
    f2h<<<4096, 256>>>((const float4*)hidden, Hs + XH);
    f2h<<<4096, 256>>>((const float4*)right,  Hs + RH);

    // 2) weights -> fp16 K-major [n][k]
    transpose_f2h<<<dim3(32, 32, 3), dim3(32, 8)>>>(Wq, Wk, Wv);

    // 3) merged projections (z=0:Q scaled 0.125, 1:K, 2:V)
    hgemm<0><<<dim3(DIM / BN, (BATCH * SEQ) / BM, 3), 256, SMEM_BYTES>>>(
        bq, bk, bv, nullptr);

    // 4) V -> V^T per batch
    transpose_h2h<<<dim3(32, 32, BATCH), dim3(32, 8)>>>();

    // 5) scores: g_scores[b][i][j] = Q[b,i,:] . K[b,j,:]  (fp32)
    hgemm<1><<<dim3(SEQ / BN, SEQ / BM, BATCH), 256, SMEM_BYTES>>>(
        nullptr, nullptr, nullptr, nullptr);

    // 6) masked softmax -> fp16 probs
    softmax_kernel<<<BATCH * SEQ, 256>>>(mask);

    // 7) context: out[b][h][q][dh] = sum_j P[b][q][j] * VT[b][h*64+dh][j]
    hgemm<2><<<dim3(SEQ / BN, SEQ / BM, BATCH), 256, SMEM_BYTES>>>(
        nullptr, nullptr, nullptr, out);
}